// round 16
// baseline (speedup 1.0000x reference)
#include <cuda_runtime.h>
#include <cuda_bf16.h>
#include <cstdint>

#define Nn   50000
#define Ee   800000
#define INF_ 500
#define HIDF 128
#define KK   10     // K (polynomial order); K+1 = 11 coefficients

// ------------------------- device scratch (static, no allocs) ---------------
__device__ int   g_deg[Nn];
__device__ int   g_cur[Nn];
__device__ int   g_off[Nn + 1];
__device__ float g_dinv[Nn];
__device__ int2  g_sw[Ee];                         // packed {src, __float_as_int(w)}
__device__ int   g_bsum[256];
__device__ int   g_boff[256];
__device__ float g_P[KK + 1][(size_t)Nn * HIDF];   // Krylov basis p_j = A^j h  (~282 MB)
__device__ float g_accL[(size_t)Nn * HIDF];
__device__ float g_accH[(size_t)Nn * HIDF];
__device__ float g_sum[4 * HIDF];                  // sumL, sqL, sumH, sqH
__device__ float g_cL[KK + 1];
__device__ float g_cH[KK + 1];
__device__ float g_alpha[2 * HIDF];                // per-branch BN scale  (L then H)
__device__ float g_beta[2 * HIDF];                 // per-branch BN shift

// m16n8k16 bf16 MMA, fp32 accumulate (standard sm_80+ PTX; compiles on sm_103)
#define MMA_BF16(d, a, b0, b1) \
    asm volatile("mma.sync.aligned.m16n8k16.row.col.f32.bf16.bf16.f32 " \
        "{%0,%1,%2,%3}, {%4,%5,%6,%7}, {%8,%9}, {%0,%1,%2,%3};" \
        : "+f"((d)[0]), "+f"((d)[1]), "+f"((d)[2]), "+f"((d)[3]) \
        : "r"((a)[0]), "r"((a)[1]), "r"((a)[2]), "r"((a)[3]), "r"(b0), "r"(b1))

// ------------------------------- small kernels -------------------------------
__global__ void k_init() {
    int i = blockIdx.x * blockDim.x + threadIdx.x;
    if (i < Nn) { g_deg[i] = 0; g_cur[i] = 0; }
    if (i < 4 * HIDF) g_sum[i] = 0.f;
    if (i == 0) g_off[Nn] = Ee;
}

__global__ void k_deg(const int* __restrict__ dst) {
    int e = blockIdx.x * blockDim.x + threadIdx.x;
    if (e < Ee) atomicAdd(&g_deg[dst[e]], 1);
}

// block sums for the scan + dinv in the same pass (one launch saved)
__global__ void k_blocksum() {
    int i = blockIdx.x * 256 + threadIdx.x;
    int v = (i < Nn) ? g_deg[i] : 0;
    if (i < Nn) g_dinv[i] = rsqrtf(fmaxf((float)v, 1.f));
    int s = v;
#pragma unroll
    for (int o = 16; o; o >>= 1) s += __shfl_down_sync(~0u, s, o);
    __shared__ int ws[8];
    if ((threadIdx.x & 31) == 0) ws[threadIdx.x >> 5] = s;
    __syncthreads();
    if (threadIdx.x < 8) {
        int t = ws[threadIdx.x];
#pragma unroll
        for (int o = 4; o; o >>= 1) t += __shfl_down_sync(0xff, t, o);
        if (threadIdx.x == 0) g_bsum[blockIdx.x] = t;
    }
}

__global__ void k_scanb(int nb) {   // single block; exclusive scan of block sums
    int t = threadIdx.x;
    int lane = t & 31, wid = t >> 5;
    int v = (t < nb) ? g_bsum[t] : 0;
    int s = v;
#pragma unroll
    for (int o = 1; o < 32; o <<= 1) {
        int u = __shfl_up_sync(~0u, s, o);
        if (lane >= o) s += u;
    }
    __shared__ int ws[8];
    if (lane == 31) ws[wid] = s;
    __syncthreads();
    if (t < 8) {
        int u = ws[t];
#pragma unroll
        for (int o = 1; o < 8; o <<= 1) {
            int q = __shfl_up_sync(0xff, u, o);
            if (t >= o) u += q;
        }
        ws[t] = u;
    }
    __syncthreads();
    int excl = s - v + (wid ? ws[wid - 1] : 0);
    if (t < nb) g_boff[t] = excl;
}

__global__ void k_scanwrite() {
    int i = blockIdx.x * 256 + threadIdx.x;
    int lane = threadIdx.x & 31, wid = threadIdx.x >> 5;
    int v = (i < Nn) ? g_deg[i] : 0;
    int s = v;
#pragma unroll
    for (int o = 1; o < 32; o <<= 1) {
        int u = __shfl_up_sync(~0u, s, o);
        if (lane >= o) s += u;
    }
    __shared__ int ws[8];
    if (lane == 31) ws[wid] = s;
    __syncthreads();
    if (threadIdx.x < 8) {
        int u = ws[threadIdx.x];
#pragma unroll
        for (int o = 1; o < 8; o <<= 1) {
            int q = __shfl_up_sync(0xff, u, o);
            if (threadIdx.x >= o) u += q;
        }
        ws[threadIdx.x] = u;
    }
    __syncthreads();
    int excl = s - v + (wid ? ws[wid - 1] : 0);
    if (i < Nn) g_off[i] = g_boff[blockIdx.x] + excl;
}

__global__ void k_scatter(const int* __restrict__ src, const int* __restrict__ dst) {
    int e = blockIdx.x * blockDim.x + threadIdx.x;
    if (e < Ee) {
        int s = src[e], d = dst[e];
        int p = atomicAdd(&g_cur[d], 1);
        int idx = g_off[d] + p;
        float w = g_dinv[s] * g_dinv[d];
        g_sw[idx] = make_int2(s, __float_as_int(w));
    }
}

// c_L[j] = gamma_L[j];  c_H[j] = (-1)^j * sum_{k>=j} gamma_H[k] * C(k,j)
__global__ void k_coeff(const float* __restrict__ gL, const float* __restrict__ gH) {
    if (threadIdx.x == 0 && blockIdx.x == 0) {
        double C[KK + 1][KK + 1];
        for (int k = 0; k <= KK; k++)
            for (int j = 0; j <= KK; j++) C[k][j] = 0.0;
        for (int k = 0; k <= KK; k++) {
            C[k][0] = 1.0; C[k][k] = 1.0;
            for (int j = 1; j < k; j++) C[k][j] = C[k - 1][j - 1] + C[k - 1][j];
        }
        for (int j = 0; j <= KK; j++) {
            double s = 0.0;
            for (int k = j; k <= KK; k++) s += (double)gH[k] * C[k][j];
            g_cH[j] = (j & 1) ? (float)(-s) : (float)s;
            g_cL[j] = gL[j];
        }
    }
}

// --------------------- GEMM1 via mma.sync bf16 (3-term split) ---------------
// C[Nn,128] = x[Nn,500] @ W[500,128] + bias.
// x = xh + xl, W = Wh + Wl (bf16 hi/lo), acc += xh*Wh + xh*Wl + xl*Wh (fp32).
// Block tile 64(M) x 128(N), 8 warps in 2x4 grid, warp tile 32x32,
// K chunks of 32 (16 chunks; tail zero-padded).
#define ASTR 34   // smem row stride in bf16 elements (68B, 4B-aligned)

__global__ __launch_bounds__(256)
void k_gemm1_mma(const float* __restrict__ A, const float* __restrict__ B,
                 const float* __restrict__ bias, float* __restrict__ C, int M) {
    __shared__ __nv_bfloat16 Ash[64][ASTR], Asl[64][ASTR];
    __shared__ __nv_bfloat16 Bsh[128][ASTR], Bsl[128][ASTR];
    int tid = threadIdx.x;
    int w = tid >> 5, lane = tid & 31;
    int g = lane >> 2, tig = lane & 3;
    int wm = w & 1, wn = w >> 1;          // warp grid 2(M) x 4(N)
    int row0 = blockIdx.x * 64;

    float acc[2][4][4];
#pragma unroll
    for (int mt = 0; mt < 2; mt++)
#pragma unroll
        for (int nf = 0; nf < 4; nf++)
#pragma unroll
            for (int i = 0; i < 4; i++) acc[mt][nf][i] = 0.f;

    for (int ch = 0; ch < 16; ch++) {
        int k0 = ch * 32;
        // ---- load A chunk: 64 rows x 32 cols fp32 -> bf16 hi/lo ----
        {
            int r = tid >> 2, c0 = (tid & 3) * 8;
            int gr = row0 + r;
#pragma unroll
            for (int i = 0; i < 8; i++) {
                int gc = k0 + c0 + i;
                float v = (gr < M && gc < INF_) ? A[(size_t)gr * INF_ + gc] : 0.f;
                __nv_bfloat16 h = __float2bfloat16(v);
                __nv_bfloat16 l = __float2bfloat16(v - __bfloat162float(h));
                Ash[r][c0 + i] = h;
                Asl[r][c0 + i] = l;
            }
        }
        // ---- load B chunk transposed: Bs[n][kk] = W[k0+kk][n] ----
        {
            int kk = tid >> 3, n0 = (tid & 7) * 16;
            int gk = k0 + kk;
#pragma unroll
            for (int i = 0; i < 16; i++) {
                float v = (gk < INF_) ? B[(size_t)gk * HIDF + n0 + i] : 0.f;
                __nv_bfloat16 h = __float2bfloat16(v);
                __nv_bfloat16 l = __float2bfloat16(v - __bfloat162float(h));
                Bsh[n0 + i][kk] = h;
                Bsl[n0 + i][kk] = l;
            }
        }
        __syncthreads();

#pragma unroll
        for (int ks = 0; ks < 2; ks++) {
            int kb = ks * 16;
            uint32_t ah[2][4], al[2][4];
#pragma unroll
            for (int mt = 0; mt < 2; mt++) {
                int r = wm * 32 + mt * 16 + g;
                int c = kb + tig * 2;
                ah[mt][0] = *(const uint32_t*)&Ash[r][c];
                ah[mt][1] = *(const uint32_t*)&Ash[r + 8][c];
                ah[mt][2] = *(const uint32_t*)&Ash[r][c + 8];
                ah[mt][3] = *(const uint32_t*)&Ash[r + 8][c + 8];
                al[mt][0] = *(const uint32_t*)&Asl[r][c];
                al[mt][1] = *(const uint32_t*)&Asl[r + 8][c];
                al[mt][2] = *(const uint32_t*)&Asl[r][c + 8];
                al[mt][3] = *(const uint32_t*)&Asl[r + 8][c + 8];
            }
#pragma unroll
            for (int nf = 0; nf < 4; nf++) {
                int n = wn * 32 + nf * 8 + g;
                uint32_t bh0 = *(const uint32_t*)&Bsh[n][kb + tig * 2];
                uint32_t bh1 = *(const uint32_t*)&Bsh[n][kb + tig * 2 + 8];
                uint32_t bl0 = *(const uint32_t*)&Bsl[n][kb + tig * 2];
                uint32_t bl1 = *(const uint32_t*)&Bsl[n][kb + tig * 2 + 8];
#pragma unroll
                for (int mt = 0; mt < 2; mt++) {
                    MMA_BF16(acc[mt][nf], ah[mt], bh0, bh1);
                    MMA_BF16(acc[mt][nf], ah[mt], bl0, bl1);
                    MMA_BF16(acc[mt][nf], al[mt], bh0, bh1);
                }
            }
        }
        __syncthreads();
    }

    // ---- epilogue: c0,c1 -> (g, 2t, 2t+1); c2,c3 -> (g+8, ...) ----
#pragma unroll
    for (int mt = 0; mt < 2; mt++) {
#pragma unroll
        for (int nf = 0; nf < 4; nf++) {
            int col = wn * 32 + nf * 8 + tig * 2;
            int gr0 = row0 + wm * 32 + mt * 16 + g;
            int gr1 = gr0 + 8;
            if (gr0 < M) {
                C[(size_t)gr0 * HIDF + col]     = acc[mt][nf][0] + bias[col];
                C[(size_t)gr0 * HIDF + col + 1] = acc[mt][nf][1] + bias[col + 1];
            }
            if (gr1 < M) {
                C[(size_t)gr1 * HIDF + col]     = acc[mt][nf][2] + bias[col];
                C[(size_t)gr1 * HIDF + col + 1] = acc[mt][nf][3] + bias[col + 1];
            }
        }
    }
}

// ------------- Epilogue GEMM via mma.sync bf16 (3-term split) ---------------
// out = relu((A*alpha + beta) @ W_up + b_up), K = 128 (4 chunks of 32).
// Both branches in one launch (blockIdx.y). BN-affine applied at A-tile load
// (pre-split, so the split operates on O(1) normalized values).
__global__ __launch_bounds__(256)
void k_gemm_ep_mma(const float* __restrict__ AL, const float* __restrict__ AH,
                   const float* __restrict__ B, const float* __restrict__ bias,
                   float* __restrict__ out, int M) {
    __shared__ __nv_bfloat16 Ash[64][ASTR], Asl[64][ASTR];
    __shared__ __nv_bfloat16 Bsh[128][ASTR], Bsl[128][ASTR];
    int br = blockIdx.y;
    const float* __restrict__ A = br ? AH : AL;
    const float* __restrict__ alpha = g_alpha + br * HIDF;
    const float* __restrict__ beta  = g_beta  + br * HIDF;
    float* __restrict__ C = out + (size_t)br * Nn * HIDF;

    int tid = threadIdx.x;
    int w = tid >> 5, lane = tid & 31;
    int g = lane >> 2, tig = lane & 3;
    int wm = w & 1, wn = w >> 1;
    int row0 = blockIdx.x * 64;

    float acc[2][4][4];
#pragma unroll
    for (int mt = 0; mt < 2; mt++)
#pragma unroll
        for (int nf = 0; nf < 4; nf++)
#pragma unroll
            for (int i = 0; i < 4; i++) acc[mt][nf][i] = 0.f;

#pragma unroll
    for (int ch = 0; ch < 4; ch++) {
        int k0 = ch * 32;
        // ---- A chunk with BN affine: 64 x 32 ----
        {
            int r = tid >> 2, c0 = (tid & 3) * 8;
            int gr = row0 + r;
#pragma unroll
            for (int i = 0; i < 8; i++) {
                int gc = k0 + c0 + i;
                float v = 0.f;
                if (gr < M) v = fmaf(A[(size_t)gr * HIDF + gc], alpha[gc], beta[gc]);
                __nv_bfloat16 h = __float2bfloat16(v);
                __nv_bfloat16 l = __float2bfloat16(v - __bfloat162float(h));
                Ash[r][c0 + i] = h;
                Asl[r][c0 + i] = l;
            }
        }
        // ---- B chunk transposed: Bs[n][kk] = W_up[k0+kk][n] ----
        {
            int kk = tid >> 3, n0 = (tid & 7) * 16;
            int gk = k0 + kk;
#pragma unroll
            for (int i = 0; i < 16; i++) {
                float v = B[(size_t)gk * HIDF + n0 + i];
                __nv_bfloat16 h = __float2bfloat16(v);
                __nv_bfloat16 l = __float2bfloat16(v - __bfloat162float(h));
                Bsh[n0 + i][kk] = h;
                Bsl[n0 + i][kk] = l;
            }
        }
        __syncthreads();

#pragma unroll
        for (int ks = 0; ks < 2; ks++) {
            int kb = ks * 16;
            uint32_t ah[2][4], al[2][4];
#pragma unroll
            for (int mt = 0; mt < 2; mt++) {
                int r = wm * 32 + mt * 16 + g;
                int c = kb + tig * 2;
                ah[mt][0] = *(const uint32_t*)&Ash[r][c];
                ah[mt][1] = *(const uint32_t*)&Ash[r + 8][c];
                ah[mt][2] = *(const uint32_t*)&Ash[r][c + 8];
                ah[mt][3] = *(const uint32_t*)&Ash[r + 8][c + 8];
                al[mt][0] = *(const uint32_t*)&Asl[r][c];
                al[mt][1] = *(const uint32_t*)&Asl[r + 8][c];
                al[mt][2] = *(const uint32_t*)&Asl[r][c + 8];
                al[mt][3] = *(const uint32_t*)&Asl[r + 8][c + 8];
            }
#pragma unroll
            for (int nf = 0; nf < 4; nf++) {
                int n = wn * 32 + nf * 8 + g;
                uint32_t bh0 = *(const uint32_t*)&Bsh[n][kb + tig * 2];
                uint32_t bh1 = *(const uint32_t*)&Bsh[n][kb + tig * 2 + 8];
                uint32_t bl0 = *(const uint32_t*)&Bsl[n][kb + tig * 2];
                uint32_t bl1 = *(const uint32_t*)&Bsl[n][kb + tig * 2 + 8];
#pragma unroll
                for (int mt = 0; mt < 2; mt++) {
                    MMA_BF16(acc[mt][nf], ah[mt], bh0, bh1);
                    MMA_BF16(acc[mt][nf], ah[mt], bl0, bl1);
                    MMA_BF16(acc[mt][nf], al[mt], bh0, bh1);
                }
            }
        }
        __syncthreads();
    }

#pragma unroll
    for (int mt = 0; mt < 2; mt++) {
#pragma unroll
        for (int nf = 0; nf < 4; nf++) {
            int col = wn * 32 + nf * 8 + tig * 2;
            int gr0 = row0 + wm * 32 + mt * 16 + g;
            int gr1 = gr0 + 8;
            if (gr0 < M) {
                C[(size_t)gr0 * HIDF + col]     = fmaxf(acc[mt][nf][0] + bias[col], 0.f);
                C[(size_t)gr0 * HIDF + col + 1] = fmaxf(acc[mt][nf][1] + bias[col + 1], 0.f);
            }
            if (gr1 < M) {
                C[(size_t)gr1 * HIDF + col]     = fmaxf(acc[mt][nf][2] + bias[col], 0.f);
                C[(size_t)gr1 * HIDF + col + 1] = fmaxf(acc[mt][nf][3] + bias[col + 1], 0.f);
            }
        }
    }
}

// --------------------------- sparse propagation ------------------------------
// one warp per dst node; each lane owns a float4 (4 features). p_j = A p_{j-1}.
// Edge meta read as int4 (2 edges per LDG.128, alignment-peeled); 4 gathers
// in flight (proven R3 structure otherwise).
__global__ __launch_bounds__(256)
void k_prop(int j) {
    int node = blockIdx.x * 8 + (threadIdx.x >> 5);
    if (node >= Nn) return;
    int lane = threadIdx.x & 31;
    const float4* __restrict__ tin = (const float4*)g_P[j - 1];
    float4* __restrict__ tout = (float4*)g_P[j];
    int beg = g_off[node], end = g_off[node + 1];
    float sx = 0.f, sy = 0.f, sz = 0.f, sw = 0.f;
    int e = beg;
    // peel to 16B alignment for int4 meta loads (g_sw element = 8B)
    if ((e & 1) && e < end) {
        int2 a0 = g_sw[e];
        float w0 = __int_as_float(a0.y);
        float4 v0 = __ldg(&tin[a0.x * 32 + lane]);
        sx = fmaf(w0, v0.x, sx); sy = fmaf(w0, v0.y, sy);
        sz = fmaf(w0, v0.z, sz); sw = fmaf(w0, v0.w, sw);
        e++;
    }
    for (; e + 4 <= end; e += 4) {
        int4 m01 = *(const int4*)&g_sw[e];       // {src0, w0, src1, w1}
        int4 m23 = *(const int4*)&g_sw[e + 2];   // {src2, w2, src3, w3}
        float4 v0 = __ldg(&tin[m01.x * 32 + lane]);
        float4 v1 = __ldg(&tin[m01.z * 32 + lane]);
        float4 v2 = __ldg(&tin[m23.x * 32 + lane]);
        float4 v3 = __ldg(&tin[m23.z * 32 + lane]);
        float w0 = __int_as_float(m01.y), w1 = __int_as_float(m01.w);
        float w2 = __int_as_float(m23.y), w3 = __int_as_float(m23.w);
        sx = fmaf(w0, v0.x, sx); sy = fmaf(w0, v0.y, sy);
        sz = fmaf(w0, v0.z, sz); sw = fmaf(w0, v0.w, sw);
        sx = fmaf(w1, v1.x, sx); sy = fmaf(w1, v1.y, sy);
        sz = fmaf(w1, v1.z, sz); sw = fmaf(w1, v1.w, sw);
        sx = fmaf(w2, v2.x, sx); sy = fmaf(w2, v2.y, sy);
        sz = fmaf(w2, v2.z, sz); sw = fmaf(w2, v2.w, sw);
        sx = fmaf(w3, v3.x, sx); sy = fmaf(w3, v3.y, sy);
        sz = fmaf(w3, v3.z, sz); sw = fmaf(w3, v3.w, sw);
    }
    for (; e < end; e++) {
        int2 a0 = g_sw[e];
        float w0 = __int_as_float(a0.y);
        float4 v0 = __ldg(&tin[a0.x * 32 + lane]);
        sx = fmaf(w0, v0.x, sx); sy = fmaf(w0, v0.y, sy);
        sz = fmaf(w0, v0.z, sz); sw = fmaf(w0, v0.w, sw);
    }
    tout[node * 32 + lane] = make_float4(sx, sy, sz, sw);
}

// --------------------------- combine + BN partials ---------------------------
__global__ __launch_bounds__(256)
void k_combine() {
    int tid = threadIdx.x;
    int fq = tid & 31;
    int wid = tid >> 5;
    float cl[KK + 1], ch[KK + 1];
#pragma unroll
    for (int j = 0; j <= KK; j++) { cl[j] = g_cL[j]; ch[j] = g_cH[j]; }

    float4 psL = {0, 0, 0, 0}, pqL = {0, 0, 0, 0};
    float4 psH = {0, 0, 0, 0}, pqH = {0, 0, 0, 0};

    for (int node = blockIdx.x * 8 + wid; node < Nn; node += gridDim.x * 8) {
        int base = node * 32 + fq;
        float4 aL = {0, 0, 0, 0}, aH = {0, 0, 0, 0};
#pragma unroll
        for (int j = 0; j <= KK; j++) {
            float4 p = ((const float4*)g_P[j])[base];
            aL.x = fmaf(cl[j], p.x, aL.x); aL.y = fmaf(cl[j], p.y, aL.y);
            aL.z = fmaf(cl[j], p.z, aL.z); aL.w = fmaf(cl[j], p.w, aL.w);
            aH.x = fmaf(ch[j], p.x, aH.x); aH.y = fmaf(ch[j], p.y, aH.y);
            aH.z = fmaf(ch[j], p.z, aH.z); aH.w = fmaf(ch[j], p.w, aH.w);
        }
        ((float4*)g_accL)[base] = aL;
        ((float4*)g_accH)[base] = aH;
        psL.x += aL.x; psL.y += aL.y; psL.z += aL.z; psL.w += aL.w;
        pqL.x = fmaf(aL.x, aL.x, pqL.x); pqL.y = fmaf(aL.y, aL.y, pqL.y);
        pqL.z = fmaf(aL.z, aL.z, pqL.z); pqL.w = fmaf(aL.w, aL.w, pqL.w);
        psH.x += aH.x; psH.y += aH.y; psH.z += aH.z; psH.w += aH.w;
        pqH.x = fmaf(aH.x, aH.x, pqH.x); pqH.y = fmaf(aH.y, aH.y, pqH.y);
        pqH.z = fmaf(aH.z, aH.z, pqH.z); pqH.w = fmaf(aH.w, aH.w, pqH.w);
    }

    __shared__ float4 sh[4][256];
    sh[0][tid] = psL; sh[1][tid] = pqL; sh[2][tid] = psH; sh[3][tid] = pqH;
    __syncthreads();
    if (tid < 32) {
        float4 a0 = sh[0][tid], a1 = sh[1][tid], a2 = sh[2][tid], a3 = sh[3][tid];
#pragma unroll
        for (int w = 1; w < 8; w++) {
            float4 t;
            t = sh[0][tid + 32 * w]; a0.x += t.x; a0.y += t.y; a0.z += t.z; a0.w += t.w;
            t = sh[1][tid + 32 * w]; a1.x += t.x; a1.y += t.y; a1.z += t.z; a1.w += t.w;
            t = sh[2][tid + 32 * w]; a2.x += t.x; a2.y += t.y; a2.z += t.z; a2.w += t.w;
            t = sh[3][tid + 32 * w]; a3.x += t.x; a3.y += t.y; a3.z += t.z; a3.w += t.w;
        }
        int f = tid * 4;
        atomicAdd(&g_sum[0 * HIDF + f + 0], a0.x); atomicAdd(&g_sum[0 * HIDF + f + 1], a0.y);
        atomicAdd(&g_sum[0 * HIDF + f + 2], a0.z); atomicAdd(&g_sum[0 * HIDF + f + 3], a0.w);
        atomicAdd(&g_sum[1 * HIDF + f + 0], a1.x); atomicAdd(&g_sum[1 * HIDF + f + 1], a1.y);
        atomicAdd(&g_sum[1 * HIDF + f + 2], a1.z); atomicAdd(&g_sum[1 * HIDF + f + 3], a1.w);
        atomicAdd(&g_sum[2 * HIDF + f + 0], a2.x); atomicAdd(&g_sum[2 * HIDF + f + 1], a2.y);
        atomicAdd(&g_sum[2 * HIDF + f + 2], a2.z); atomicAdd(&g_sum[2 * HIDF + f + 3], a2.w);
        atomicAdd(&g_sum[3 * HIDF + f + 0], a3.x); atomicAdd(&g_sum[3 * HIDF + f + 1], a3.y);
        atomicAdd(&g_sum[3 * HIDF + f + 2], a3.z); atomicAdd(&g_sum[3 * HIDF + f + 3], a3.w);
    }
}

__global__ void k_bnfinal(const float* __restrict__ bn_scale,
                          const float* __restrict__ bn_shift) {
    int f = threadIdx.x;
    if (f < HIDF) {
        const float invN = 1.f / (float)Nn;
        float mu = g_sum[f] * invN;
        float var = g_sum[HIDF + f] * invN - mu * mu;
        float a = rsqrtf(var + 1e-5f) * bn_scale[f];
        g_alpha[f] = a;
        g_beta[f] = bn_shift[f] - mu * a;
        mu = g_sum[2 * HIDF + f] * invN;
        var = g_sum[3 * HIDF + f] * invN - mu * mu;
        a = rsqrtf(var + 1e-5f) * bn_scale[f];
        g_alpha[HIDF + f] = a;
        g_beta[HIDF + f] = bn_shift[f] - mu * a;
    }
}

// ------------------------------- launcher ------------------------------------
extern "C" void kernel_launch(void* const* d_in, const int* in_sizes, int n_in,
                              void* d_out, int out_size) {
    const float* x    = (const float*)d_in[0];
    const int*   ei   = (const int*)d_in[1];
    const float* W_in = (const float*)d_in[2];
    const float* b_in = (const float*)d_in[3];
    const float* gL   = (const float*)d_in[4];
    const float* gH   = (const float*)d_in[5];
    const float* bns  = (const float*)d_in[6];
    const float* bnb  = (const float*)d_in[7];
    const float* W_up = (const float*)d_in[8];
    const float* b_up = (const float*)d_in[9];
    float* out = (float*)d_out;

    const int* src = ei;
    const int* dst = ei + Ee;

    void *pP, *pAL, *pAH;
    cudaGetSymbolAddress(&pP,  g_P);
    cudaGetSymbolAddress(&pAL, g_accL);
    cudaGetSymbolAddress(&pAH, g_accH);
    float* P0   = (float*)pP;                  // g_P[0]
    float* accL = (float*)pAL;
    float* accH = (float*)pAH;

    const int nblkN = (Nn + 255) / 256;   // 196
    const int nblkE = (Ee + 255) / 256;   // 3125
    const int gemmB = (Nn + 63) / 64;     // 782

    k_init<<<nblkN, 256>>>();
    k_deg<<<nblkE, 256>>>(dst);
    k_blocksum<<<nblkN, 256>>>();
    k_scanb<<<1, 256>>>(nblkN);
    k_scanwrite<<<nblkN, 256>>>();
    k_scatter<<<nblkE, 256>>>(src, dst);
    k_coeff<<<1, 32>>>(gL, gH);

    // p_0 = h = x @ W_in + b_in   (tensor-core bf16 3-term split via mma.sync)
    k_gemm1_mma<<<gemmB, 256>>>(x, W_in, b_in, P0, Nn);

    // Krylov chain p_j = A p_{j-1}
    for (int j = 1; j <= KK; j++)
        k_prop<<<(Nn + 7) / 8, 256>>>(j);

    // acc_L / acc_H + BN statistics
    k_combine<<<592, 256>>>();
    k_bnfinal<<<1, 128>>>(bns, bnb);

    // Z = relu(BN(acc) @ W_up + b_up), both branches, tensor-core path
    dim3 epg(gemmB, 2);
    k_gemm_ep_mma<<<epg, 256>>>(accL, accH, W_up, b_up, out, Nn);
}

// round 17
// speedup vs baseline: 1.1345x; 1.1345x over previous
#include <cuda_runtime.h>
#include <cuda_bf16.h>
#include <cuda_fp16.h>
#include <cstdint>

#define Nn   50000
#define Ee   800000
#define INF_ 500
#define HIDF 128
#define KK   10     // K (polynomial order); K+1 = 11 coefficients

// ------------------------- device scratch (static, no allocs) ---------------
__device__ int    g_deg[Nn];
__device__ int    g_cur[Nn];
__device__ int    g_off[Nn + 1];
__device__ float  g_dinv[Nn];
__device__ int2   g_sw[Ee];                        // packed {src, __float_as_int(w)}
__device__ int    g_bsum[256];
__device__ int    g_boff[256];
__device__ float  g_P[3][(size_t)Nn * HIDF];       // p0..p2 fp32 (77 MB)
__device__ __half g_Ph[8][(size_t)Nn * HIDF];      // p3..p10 fp16 (102 MB)
__device__ float  g_accL[(size_t)Nn * HIDF];
__device__ float  g_accH[(size_t)Nn * HIDF];
__device__ float  g_sum[4 * HIDF];                 // sumL, sqL, sumH, sqH
__device__ float  g_cL[KK + 1];
__device__ float  g_cH[KK + 1];
__device__ float  g_alpha[2 * HIDF];               // per-branch BN scale (L then H)
__device__ float  g_beta[2 * HIDF];                // per-branch BN shift

// m16n8k16 bf16 MMA, fp32 accumulate (standard sm_80+ PTX; compiles on sm_103)
#define MMA_BF16(d, a, b0, b1) \
    asm volatile("mma.sync.aligned.m16n8k16.row.col.f32.bf16.bf16.f32 " \
        "{%0,%1,%2,%3}, {%4,%5,%6,%7}, {%8,%9}, {%0,%1,%2,%3};" \
        : "+f"((d)[0]), "+f"((d)[1]), "+f"((d)[2]), "+f"((d)[3]) \
        : "r"((a)[0]), "r"((a)[1]), "r"((a)[2]), "r"((a)[3]), "r"(b0), "r"(b1))

// ------------------------------- small kernels -------------------------------
__global__ void k_init() {
    int i = blockIdx.x * blockDim.x + threadIdx.x;
    if (i < Nn) { g_deg[i] = 0; g_cur[i] = 0; }
    if (i < 4 * HIDF) g_sum[i] = 0.f;
    if (i == 0) g_off[Nn] = Ee;
}

__global__ void k_deg(const int* __restrict__ dst) {
    int e = blockIdx.x * blockDim.x + threadIdx.x;
    if (e < Ee) atomicAdd(&g_deg[dst[e]], 1);
}

__global__ void k_dinv() {
    int i = blockIdx.x * blockDim.x + threadIdx.x;
    if (i < Nn) g_dinv[i] = rsqrtf(fmaxf((float)g_deg[i], 1.f));
}

// ------------- multi-block exclusive scan of g_deg -> g_off ------------------
__global__ void k_blocksum() {
    int i = blockIdx.x * 256 + threadIdx.x;
    int v = (i < Nn) ? g_deg[i] : 0;
#pragma unroll
    for (int o = 16; o; o >>= 1) v += __shfl_down_sync(~0u, v, o);
    __shared__ int ws[8];
    if ((threadIdx.x & 31) == 0) ws[threadIdx.x >> 5] = v;
    __syncthreads();
    if (threadIdx.x < 8) {
        int t = ws[threadIdx.x];
#pragma unroll
        for (int o = 4; o; o >>= 1) t += __shfl_down_sync(0xff, t, o);
        if (threadIdx.x == 0) g_bsum[blockIdx.x] = t;
    }
}

__global__ void k_scanb(int nb) {
    int t = threadIdx.x;
    int lane = t & 31, wid = t >> 5;
    int v = (t < nb) ? g_bsum[t] : 0;
    int s = v;
#pragma unroll
    for (int o = 1; o < 32; o <<= 1) {
        int u = __shfl_up_sync(~0u, s, o);
        if (lane >= o) s += u;
    }
    __shared__ int ws[8];
    if (lane == 31) ws[wid] = s;
    __syncthreads();
    if (t < 8) {
        int u = ws[t];
#pragma unroll
        for (int o = 1; o < 8; o <<= 1) {
            int q = __shfl_up_sync(0xff, u, o);
            if (t >= o) u += q;
        }
        ws[t] = u;
    }
    __syncthreads();
    int excl = s - v + (wid ? ws[wid - 1] : 0);
    if (t < nb) g_boff[t] = excl;
}

__global__ void k_scanwrite() {
    int i = blockIdx.x * 256 + threadIdx.x;
    int lane = threadIdx.x & 31, wid = threadIdx.x >> 5;
    int v = (i < Nn) ? g_deg[i] : 0;
    int s = v;
#pragma unroll
    for (int o = 1; o < 32; o <<= 1) {
        int u = __shfl_up_sync(~0u, s, o);
        if (lane >= o) s += u;
    }
    __shared__ int ws[8];
    if (lane == 31) ws[wid] = s;
    __syncthreads();
    if (threadIdx.x < 8) {
        int u = ws[threadIdx.x];
#pragma unroll
        for (int o = 1; o < 8; o <<= 1) {
            int q = __shfl_up_sync(0xff, u, o);
            if (threadIdx.x >= o) u += q;
        }
        ws[threadIdx.x] = u;
    }
    __syncthreads();
    int excl = s - v + (wid ? ws[wid - 1] : 0);
    if (i < Nn) g_off[i] = g_boff[blockIdx.x] + excl;
}

__global__ void k_scatter(const int* __restrict__ src, const int* __restrict__ dst) {
    int e = blockIdx.x * blockDim.x + threadIdx.x;
    if (e < Ee) {
        int s = src[e], d = dst[e];
        int p = atomicAdd(&g_cur[d], 1);
        int idx = g_off[d] + p;
        float w = g_dinv[s] * g_dinv[d];
        g_sw[idx] = make_int2(s, __float_as_int(w));
    }
}

// c_L[j] = gamma_L[j];  c_H[j] = (-1)^j * sum_{k>=j} gamma_H[k] * C(k,j)
__global__ void k_coeff(const float* __restrict__ gL, const float* __restrict__ gH) {
    if (threadIdx.x == 0 && blockIdx.x == 0) {
        double C[KK + 1][KK + 1];
        for (int k = 0; k <= KK; k++)
            for (int j = 0; j <= KK; j++) C[k][j] = 0.0;
        for (int k = 0; k <= KK; k++) {
            C[k][0] = 1.0; C[k][k] = 1.0;
            for (int j = 1; j < k; j++) C[k][j] = C[k - 1][j - 1] + C[k - 1][j];
        }
        for (int j = 0; j <= KK; j++) {
            double s = 0.0;
            for (int k = j; k <= KK; k++) s += (double)gH[k] * C[k][j];
            g_cH[j] = (j & 1) ? (float)(-s) : (float)s;
            g_cL[j] = gL[j];
        }
    }
}

// --------------------- GEMM1 via mma.sync bf16 (3-term split) ---------------
#define ASTR 34   // smem row stride in bf16 elements (68B, 4B-aligned)

__global__ __launch_bounds__(256)
void k_gemm1_mma(const float* __restrict__ A, const float* __restrict__ B,
                 const float* __restrict__ bias, float* __restrict__ C, int M) {
    __shared__ __nv_bfloat16 Ash[64][ASTR], Asl[64][ASTR];
    __shared__ __nv_bfloat16 Bsh[128][ASTR], Bsl[128][ASTR];
    int tid = threadIdx.x;
    int w = tid >> 5, lane = tid & 31;
    int g = lane >> 2, tig = lane & 3;
    int wm = w & 1, wn = w >> 1;          // warp grid 2(M) x 4(N)
    int row0 = blockIdx.x * 64;

    float acc[2][4][4];
#pragma unroll
    for (int mt = 0; mt < 2; mt++)
#pragma unroll
        for (int nf = 0; nf < 4; nf++)
#pragma unroll
            for (int i = 0; i < 4; i++) acc[mt][nf][i] = 0.f;

    for (int ch = 0; ch < 16; ch++) {
        int k0 = ch * 32;
        {
            int r = tid >> 2, c0 = (tid & 3) * 8;
            int gr = row0 + r;
#pragma unroll
            for (int i = 0; i < 8; i++) {
                int gc = k0 + c0 + i;
                float v = (gr < M && gc < INF_) ? A[(size_t)gr * INF_ + gc] : 0.f;
                __nv_bfloat16 h = __float2bfloat16(v);
                __nv_bfloat16 l = __float2bfloat16(v - __bfloat162float(h));
                Ash[r][c0 + i] = h;
                Asl[r][c0 + i] = l;
            }
        }
        {
            int kk = tid >> 3, n0 = (tid & 7) * 16;
            int gk = k0 + kk;
#pragma unroll
            for (int i = 0; i < 16; i++) {
                float v = (gk < INF_) ? B[(size_t)gk * HIDF + n0 + i] : 0.f;
                __nv_bfloat16 h = __float2bfloat16(v);
                __nv_bfloat16 l = __float2bfloat16(v - __bfloat162float(h));
                Bsh[n0 + i][kk] = h;
                Bsl[n0 + i][kk] = l;
            }
        }
        __syncthreads();

#pragma unroll
        for (int ks = 0; ks < 2; ks++) {
            int kb = ks * 16;
            uint32_t ah[2][4], al[2][4];
#pragma unroll
            for (int mt = 0; mt < 2; mt++) {
                int r = wm * 32 + mt * 16 + g;
                int c = kb + tig * 2;
                ah[mt][0] = *(const uint32_t*)&Ash[r][c];
                ah[mt][1] = *(const uint32_t*)&Ash[r + 8][c];
                ah[mt][2] = *(const uint32_t*)&Ash[r][c + 8];
                ah[mt][3] = *(const uint32_t*)&Ash[r + 8][c + 8];
                al[mt][0] = *(const uint32_t*)&Asl[r][c];
                al[mt][1] = *(const uint32_t*)&Asl[r + 8][c];
                al[mt][2] = *(const uint32_t*)&Asl[r][c + 8];
                al[mt][3] = *(const uint32_t*)&Asl[r + 8][c + 8];
            }
#pragma unroll
            for (int nf = 0; nf < 4; nf++) {
                int n = wn * 32 + nf * 8 + g;
                uint32_t bh0 = *(const uint32_t*)&Bsh[n][kb + tig * 2];
                uint32_t bh1 = *(const uint32_t*)&Bsh[n][kb + tig * 2 + 8];
                uint32_t bl0 = *(const uint32_t*)&Bsl[n][kb + tig * 2];
                uint32_t bl1 = *(const uint32_t*)&Bsl[n][kb + tig * 2 + 8];
#pragma unroll
                for (int mt = 0; mt < 2; mt++) {
                    MMA_BF16(acc[mt][nf], ah[mt], bh0, bh1);
                    MMA_BF16(acc[mt][nf], ah[mt], bl0, bl1);
                    MMA_BF16(acc[mt][nf], al[mt], bh0, bh1);
                }
            }
        }
        __syncthreads();
    }

#pragma unroll
    for (int mt = 0; mt < 2; mt++) {
#pragma unroll
        for (int nf = 0; nf < 4; nf++) {
            int col = wn * 32 + nf * 8 + tig * 2;
            int gr0 = row0 + wm * 32 + mt * 16 + g;
            int gr1 = gr0 + 8;
            if (gr0 < M) {
                C[(size_t)gr0 * HIDF + col]     = acc[mt][nf][0] + bias[col];
                C[(size_t)gr0 * HIDF + col + 1] = acc[mt][nf][1] + bias[col + 1];
            }
            if (gr1 < M) {
                C[(size_t)gr1 * HIDF + col]     = acc[mt][nf][2] + bias[col];
                C[(size_t)gr1 * HIDF + col + 1] = acc[mt][nf][3] + bias[col + 1];
            }
        }
    }
}

// ------------- Epilogue GEMM via mma.sync bf16 (3-term split) ---------------
__global__ __launch_bounds__(256)
void k_gemm_ep_mma(const float* __restrict__ AL, const float* __restrict__ AH,
                   const float* __restrict__ B, const float* __restrict__ bias,
                   float* __restrict__ out, int M) {
    __shared__ __nv_bfloat16 Ash[64][ASTR], Asl[64][ASTR];
    __shared__ __nv_bfloat16 Bsh[128][ASTR], Bsl[128][ASTR];
    int br = blockIdx.y;
    const float* __restrict__ A = br ? AH : AL;
    const float* __restrict__ alpha = g_alpha + br * HIDF;
    const float* __restrict__ beta  = g_beta  + br * HIDF;
    float* __restrict__ C = out + (size_t)br * Nn * HIDF;

    int tid = threadIdx.x;
    int w = tid >> 5, lane = tid & 31;
    int g = lane >> 2, tig = lane & 3;
    int wm = w & 1, wn = w >> 1;
    int row0 = blockIdx.x * 64;

    float acc[2][4][4];
#pragma unroll
    for (int mt = 0; mt < 2; mt++)
#pragma unroll
        for (int nf = 0; nf < 4; nf++)
#pragma unroll
            for (int i = 0; i < 4; i++) acc[mt][nf][i] = 0.f;

#pragma unroll
    for (int ch = 0; ch < 4; ch++) {
        int k0 = ch * 32;
        {
            int r = tid >> 2, c0 = (tid & 3) * 8;
            int gr = row0 + r;
#pragma unroll
            for (int i = 0; i < 8; i++) {
                int gc = k0 + c0 + i;
                float v = 0.f;
                if (gr < M) v = fmaf(A[(size_t)gr * HIDF + gc], alpha[gc], beta[gc]);
                __nv_bfloat16 h = __float2bfloat16(v);
                __nv_bfloat16 l = __float2bfloat16(v - __bfloat162float(h));
                Ash[r][c0 + i] = h;
                Asl[r][c0 + i] = l;
            }
        }
        {
            int kk = tid >> 3, n0 = (tid & 7) * 16;
            int gk = k0 + kk;
#pragma unroll
            for (int i = 0; i < 16; i++) {
                float v = B[(size_t)gk * HIDF + n0 + i];
                __nv_bfloat16 h = __float2bfloat16(v);
                __nv_bfloat16 l = __float2bfloat16(v - __bfloat162float(h));
                Bsh[n0 + i][kk] = h;
                Bsl[n0 + i][kk] = l;
            }
        }
        __syncthreads();

#pragma unroll
        for (int ks = 0; ks < 2; ks++) {
            int kb = ks * 16;
            uint32_t ah[2][4], al[2][4];
#pragma unroll
            for (int mt = 0; mt < 2; mt++) {
                int r = wm * 32 + mt * 16 + g;
                int c = kb + tig * 2;
                ah[mt][0] = *(const uint32_t*)&Ash[r][c];
                ah[mt][1] = *(const uint32_t*)&Ash[r + 8][c];
                ah[mt][2] = *(const uint32_t*)&Ash[r][c + 8];
                ah[mt][3] = *(const uint32_t*)&Ash[r + 8][c + 8];
                al[mt][0] = *(const uint32_t*)&Asl[r][c];
                al[mt][1] = *(const uint32_t*)&Asl[r + 8][c];
                al[mt][2] = *(const uint32_t*)&Asl[r][c + 8];
                al[mt][3] = *(const uint32_t*)&Asl[r + 8][c + 8];
            }
#pragma unroll
            for (int nf = 0; nf < 4; nf++) {
                int n = wn * 32 + nf * 8 + g;
                uint32_t bh0 = *(const uint32_t*)&Bsh[n][kb + tig * 2];
                uint32_t bh1 = *(const uint32_t*)&Bsh[n][kb + tig * 2 + 8];
                uint32_t bl0 = *(const uint32_t*)&Bsl[n][kb + tig * 2];
                uint32_t bl1 = *(const uint32_t*)&Bsl[n][kb + tig * 2 + 8];
#pragma unroll
                for (int mt = 0; mt < 2; mt++) {
                    MMA_BF16(acc[mt][nf], ah[mt], bh0, bh1);
                    MMA_BF16(acc[mt][nf], ah[mt], bl0, bl1);
                    MMA_BF16(acc[mt][nf], al[mt], bh0, bh1);
                }
            }
        }
        __syncthreads();
    }

#pragma unroll
    for (int mt = 0; mt < 2; mt++) {
#pragma unroll
        for (int nf = 0; nf < 4; nf++) {
            int col = wn * 32 + nf * 8 + tig * 2;
            int gr0 = row0 + wm * 32 + mt * 16 + g;
            int gr1 = gr0 + 8;
            if (gr0 < M) {
                C[(size_t)gr0 * HIDF + col]     = fmaxf(acc[mt][nf][0] + bias[col], 0.f);
                C[(size_t)gr0 * HIDF + col + 1] = fmaxf(acc[mt][nf][1] + bias[col + 1], 0.f);
            }
            if (gr1 < M) {
                C[(size_t)gr1 * HIDF + col]     = fmaxf(acc[mt][nf][2] + bias[col], 0.f);
                C[(size_t)gr1 * HIDF + col + 1] = fmaxf(acc[mt][nf][3] + bias[col + 1], 0.f);
            }
        }
    }
}

// --------------------------- sparse propagation ------------------------------
// Proven structure: one warp per dst node, lane owns 4 features, int2 meta,
// 4 gathers in flight. Three dtype variants: f32->f32, f32->f16, f16->f16.
// Accumulation is always fp32.

__global__ __launch_bounds__(256)
void k_prop_ff(const float* __restrict__ pin, float* __restrict__ pout) {
    int node = blockIdx.x * 8 + (threadIdx.x >> 5);
    if (node >= Nn) return;
    int lane = threadIdx.x & 31;
    const float4* __restrict__ tin = (const float4*)pin;
    float4* __restrict__ tout = (float4*)pout;
    int beg = g_off[node], end = g_off[node + 1];
    float sx = 0.f, sy = 0.f, sz = 0.f, sw = 0.f;
    int e = beg;
    for (; e + 4 <= end; e += 4) {
        int2 a0 = g_sw[e],     a1 = g_sw[e + 1];
        int2 a2 = g_sw[e + 2], a3 = g_sw[e + 3];
        float4 v0 = __ldg(&tin[a0.x * 32 + lane]);
        float4 v1 = __ldg(&tin[a1.x * 32 + lane]);
        float4 v2 = __ldg(&tin[a2.x * 32 + lane]);
        float4 v3 = __ldg(&tin[a3.x * 32 + lane]);
        float w0 = __int_as_float(a0.y), w1 = __int_as_float(a1.y);
        float w2 = __int_as_float(a2.y), w3 = __int_as_float(a3.y);
        sx = fmaf(w0, v0.x, sx); sy = fmaf(w0, v0.y, sy);
        sz = fmaf(w0, v0.z, sz); sw = fmaf(w0, v0.w, sw);
        sx = fmaf(w1, v1.x, sx); sy = fmaf(w1, v1.y, sy);
        sz = fmaf(w1, v1.z, sz); sw = fmaf(w1, v1.w, sw);
        sx = fmaf(w2, v2.x, sx); sy = fmaf(w2, v2.y, sy);
        sz = fmaf(w2, v2.z, sz); sw = fmaf(w2, v2.w, sw);
        sx = fmaf(w3, v3.x, sx); sy = fmaf(w3, v3.y, sy);
        sz = fmaf(w3, v3.z, sz); sw = fmaf(w3, v3.w, sw);
    }
    for (; e < end; e++) {
        int2 a0 = g_sw[e];
        float w0 = __int_as_float(a0.y);
        float4 v0 = __ldg(&tin[a0.x * 32 + lane]);
        sx = fmaf(w0, v0.x, sx); sy = fmaf(w0, v0.y, sy);
        sz = fmaf(w0, v0.z, sz); sw = fmaf(w0, v0.w, sw);
    }
    tout[node * 32 + lane] = make_float4(sx, sy, sz, sw);
}

__device__ __forceinline__ uint2 pack_h4(float sx, float sy, float sz, float sw) {
    __half2 lo = __floats2half2_rn(sx, sy);
    __half2 hi = __floats2half2_rn(sz, sw);
    uint2 r;
    r.x = *(uint32_t*)&lo;
    r.y = *(uint32_t*)&hi;
    return r;
}

__global__ __launch_bounds__(256)
void k_prop_fh(const float* __restrict__ pin, __half* __restrict__ pout) {
    int node = blockIdx.x * 8 + (threadIdx.x >> 5);
    if (node >= Nn) return;
    int lane = threadIdx.x & 31;
    const float4* __restrict__ tin = (const float4*)pin;
    uint2* __restrict__ tout = (uint2*)pout;
    int beg = g_off[node], end = g_off[node + 1];
    float sx = 0.f, sy = 0.f, sz = 0.f, sw = 0.f;
    int e = beg;
    for (; e + 4 <= end; e += 4) {
        int2 a0 = g_sw[e],     a1 = g_sw[e + 1];
        int2 a2 = g_sw[e + 2], a3 = g_sw[e + 3];
        float4 v0 = __ldg(&tin[a0.x * 32 + lane]);
        float4 v1 = __ldg(&tin[a1.x * 32 + lane]);
        float4 v2 = __ldg(&tin[a2.x * 32 + lane]);
        float4 v3 = __ldg(&tin[a3.x * 32 + lane]);
        float w0 = __int_as_float(a0.y), w1 = __int_as_float(a1.y);
        float w2 = __int_as_float(a2.y), w3 = __int_as_float(a3.y);
        sx = fmaf(w0, v0.x, sx); sy = fmaf(w0, v0.y, sy);
        sz = fmaf(w0, v0.z, sz); sw = fmaf(w0, v0.w, sw);
        sx = fmaf(w1, v1.x, sx); sy = fmaf(w1, v1.y, sy);
        sz = fmaf(w1, v1.z, sz); sw = fmaf(w1, v1.w, sw);
        sx = fmaf(w2, v2.x, sx); sy = fmaf(w2, v2.y, sy);
        sz = fmaf(w2, v2.z, sz); sw = fmaf(w2, v2.w, sw);
        sx = fmaf(w3, v3.x, sx); sy = fmaf(w3, v3.y, sy);
        sz = fmaf(w3, v3.z, sz); sw = fmaf(w3, v3.w, sw);
    }
    for (; e < end; e++) {
        int2 a0 = g_sw[e];
        float w0 = __int_as_float(a0.y);
        float4 v0 = __ldg(&tin[a0.x * 32 + lane]);
        sx = fmaf(w0, v0.x, sx); sy = fmaf(w0, v0.y, sy);
        sz = fmaf(w0, v0.z, sz); sw = fmaf(w0, v0.w, sw);
    }
    tout[node * 32 + lane] = pack_h4(sx, sy, sz, sw);
}

__global__ __launch_bounds__(256)
void k_prop_hh(const __half* __restrict__ pin, __half* __restrict__ pout) {
    int node = blockIdx.x * 8 + (threadIdx.x >> 5);
    if (node >= Nn) return;
    int lane = threadIdx.x & 31;
    const uint2* __restrict__ tin = (const uint2*)pin;
    uint2* __restrict__ tout = (uint2*)pout;
    int beg = g_off[node], end = g_off[node + 1];
    float sx = 0.f, sy = 0.f, sz = 0.f, sw = 0.f;
    int e = beg;
    for (; e + 4 <= end; e += 4) {
        int2 a0 = g_sw[e],     a1 = g_sw[e + 1];
        int2 a2 = g_sw[e + 2], a3 = g_sw[e + 3];
        uint2 q0 = __ldg(&tin[a0.x * 32 + lane]);
        uint2 q1 = __ldg(&tin[a1.x * 32 + lane]);
        uint2 q2 = __ldg(&tin[a2.x * 32 + lane]);
        uint2 q3 = __ldg(&tin[a3.x * 32 + lane]);
        float w0 = __int_as_float(a0.y), w1 = __int_as_float(a1.y);
        float w2 = __int_as_float(a2.y), w3 = __int_as_float(a3.y);
        float2 f0a = __half22float2(*(__half2*)&q0.x), f0b = __half22float2(*(__half2*)&q0.y);
        float2 f1a = __half22float2(*(__half2*)&q1.x), f1b = __half22float2(*(__half2*)&q1.y);
        float2 f2a = __half22float2(*(__half2*)&q2.x), f2b = __half22float2(*(__half2*)&q2.y);
        float2 f3a = __half22float2(*(__half2*)&q3.x), f3b = __half22float2(*(__half2*)&q3.y);
        sx = fmaf(w0, f0a.x, sx); sy = fmaf(w0, f0a.y, sy);
        sz = fmaf(w0, f0b.x, sz); sw = fmaf(w0, f0b.y, sw);
        sx = fmaf(w1, f1a.x, sx); sy = fmaf(w1, f1a.y, sy);
        sz = fmaf(w1, f1b.x, sz); sw = fmaf(w1, f1b.y, sw);
        sx = fmaf(w2, f2a.x, sx); sy = fmaf(w2, f2a.y, sy);
        sz = fmaf(w2, f2b.x, sz); sw = fmaf(w2, f2b.y, sw);
        sx = fmaf(w3, f3a.x, sx); sy = fmaf(w3, f3a.y, sy);
        sz = fmaf(w3, f3b.x, sz); sw = fmaf(w3, f3b.y, sw);
    }
    for (; e < end; e++) {
        int2 a0 = g_sw[e];
        float w0 = __int_as_float(a0.y);
        uint2 q0 = __ldg(&tin[a0.x * 32 + lane]);
        float2 f0a = __half22float2(*(__half2*)&q0.x), f0b = __half22float2(*(__half2*)&q0.y);
        sx = fmaf(w0, f0a.x, sx); sy = fmaf(w0, f0a.y, sy);
        sz = fmaf(w0, f0b.x, sz); sw = fmaf(w0, f0b.y, sw);
    }
    tout[node * 32 + lane] = pack_h4(sx, sy, sz, sw);
}

// --------------------------- combine + BN partials ---------------------------
// acc = sum_j c[j] p_j with p0..p2 fp32, p3..p10 fp16; fp32 accumulation.
__global__ __launch_bounds__(256)
void k_combine() {
    int tid = threadIdx.x;
    int fq = tid & 31;
    int wid = tid >> 5;
    float cl[KK + 1], ch[KK + 1];
#pragma unroll
    for (int j = 0; j <= KK; j++) { cl[j] = g_cL[j]; ch[j] = g_cH[j]; }

    float4 psL = {0, 0, 0, 0}, pqL = {0, 0, 0, 0};
    float4 psH = {0, 0, 0, 0}, pqH = {0, 0, 0, 0};

    for (int node = blockIdx.x * 8 + wid; node < Nn; node += gridDim.x * 8) {
        int base = node * 32 + fq;
        float4 aL = {0, 0, 0, 0}, aH = {0, 0, 0, 0};
#pragma unroll
        for (int j = 0; j < 3; j++) {
            float4 p = ((const float4*)g_P[j])[base];
            aL.x = fmaf(cl[j], p.x, aL.x); aL.y = fmaf(cl[j], p.y, aL.y);
            aL.z = fmaf(cl[j], p.z, aL.z); aL.w = fmaf(cl[j], p.w, aL.w);
            aH.x = fmaf(ch[j], p.x, aH.x); aH.y = fmaf(ch[j], p.y, aH.y);
            aH.z = fmaf(ch[j], p.z, aH.z); aH.w = fmaf(ch[j], p.w, aH.w);
        }
#pragma unroll
        for (int j = 0; j < 8; j++) {
            uint2 q = ((const uint2*)g_Ph[j])[base];
            float2 fa = __half22float2(*(__half2*)&q.x);
            float2 fb = __half22float2(*(__half2*)&q.y);
            float cj = cl[3 + j], dj = ch[3 + j];
            aL.x = fmaf(cj, fa.x, aL.x); aL.y = fmaf(cj, fa.y, aL.y);
            aL.z = fmaf(cj, fb.x, aL.z); aL.w = fmaf(cj, fb.y, aL.w);
            aH.x = fmaf(dj, fa.x, aH.x); aH.y = fmaf(dj, fa.y, aH.y);
            aH.z = fmaf(dj, fb.x, aH.z); aH.w = fmaf(dj, fb.y, aH.w);
        }
        ((float4*)g_accL)[base] = aL;
        ((float4*)g_accH)[base] = aH;
        psL.x += aL.x; psL.y += aL.y; psL.z += aL.z; psL.w += aL.w;
        pqL.x = fmaf(aL.x, aL.x, pqL.x); pqL.y = fmaf(aL.y, aL.y, pqL.y);
        pqL.z = fmaf(aL.z, aL.z, pqL.z); pqL.w = fmaf(aL.w, aL.w, pqL.w);
        psH.x += aH.x; psH.y += aH.y; psH.z += aH.z; psH.w += aH.w;
        pqH.x = fmaf(aH.x, aH.x, pqH.x); pqH.y = fmaf(aH.y, aH.y, pqH.y);
        pqH.z = fmaf(aH.z, aH.z, pqH.z); pqH.w = fmaf(aH.w, aH.w, pqH.w);
    }

    __shared__ float4 sh[4][256];
    sh[0][tid] = psL; sh[1][tid] = pqL; sh[2][tid] = psH; sh[3][tid] = pqH;
    __syncthreads();
    if (tid < 32) {
        float4 a0 = sh[0][tid], a1 = sh[1][tid], a2 = sh[2][tid], a3 = sh[3][tid];
#pragma unroll
        for (int w = 1; w < 8; w++) {
            float4 t;
            t = sh[0][tid + 32 * w]; a0.x += t.x; a0.y += t.y; a0.z += t.z; a0.w += t.w;
            t = sh[1][tid + 32 * w]; a1.x += t.x; a1.y += t.y; a1.z += t.z; a1.w += t.w;
            t = sh[2][tid + 32 * w]; a2.x += t.x; a2.y += t.y; a2.z += t.z; a2.w += t.w;
            t = sh[3][tid + 32 * w]; a3.x += t.x; a3.y += t.y; a3.z += t.z; a3.w += t.w;
        }
        int f = tid * 4;
        atomicAdd(&g_sum[0 * HIDF + f + 0], a0.x); atomicAdd(&g_sum[0 * HIDF + f + 1], a0.y);
        atomicAdd(&g_sum[0 * HIDF + f + 2], a0.z); atomicAdd(&g_sum[0 * HIDF + f + 3], a0.w);
        atomicAdd(&g_sum[1 * HIDF + f + 0], a1.x); atomicAdd(&g_sum[1 * HIDF + f + 1], a1.y);
        atomicAdd(&g_sum[1 * HIDF + f + 2], a1.z); atomicAdd(&g_sum[1 * HIDF + f + 3], a1.w);
        atomicAdd(&g_sum[2 * HIDF + f + 0], a2.x); atomicAdd(&g_sum[2 * HIDF + f + 1], a2.y);
        atomicAdd(&g_sum[2 * HIDF + f + 2], a2.z); atomicAdd(&g_sum[2 * HIDF + f + 3], a2.w);
        atomicAdd(&g_sum[3 * HIDF + f + 0], a3.x); atomicAdd(&g_sum[3 * HIDF + f + 1], a3.y);
        atomicAdd(&g_sum[3 * HIDF + f + 2], a3.z); atomicAdd(&g_sum[3 * HIDF + f + 3], a3.w);
    }
}

__global__ void k_bnfinal(const float* __restrict__ bn_scale,
                          const float* __restrict__ bn_shift) {
    int f = threadIdx.x;
    if (f < HIDF) {
        const float invN = 1.f / (float)Nn;
        float mu = g_sum[f] * invN;
        float var = g_sum[HIDF + f] * invN - mu * mu;
        float a = rsqrtf(var + 1e-5f) * bn_scale[f];
        g_alpha[f] = a;
        g_beta[f] = bn_shift[f] - mu * a;
        mu = g_sum[2 * HIDF + f] * invN;
        var = g_sum[3 * HIDF + f] * invN - mu * mu;
        a = rsqrtf(var + 1e-5f) * bn_scale[f];
        g_alpha[HIDF + f] = a;
        g_beta[HIDF + f] = bn_shift[f] - mu * a;
    }
}

// ------------------------------- launcher ------------------------------------
extern "C" void kernel_launch(void* const* d_in, const int* in_sizes, int n_in,
                              void* d_out, int out_size) {
    const float* x    = (const float*)d_in[0];
    const int*   ei   = (const int*)d_in[1];
    const float* W_in = (const float*)d_in[2];
    const float* b_in = (const float*)d_in[3];
    const float* gL   = (const float*)d_in[4];
    const float* gH   = (const float*)d_in[5];
    const float* bns  = (const float*)d_in[6];
    const float* bnb  = (const float*)d_in[7];
    const float* W_up = (const float*)d_in[8];
    const float* b_up = (const float*)d_in[9];
    float* out = (float*)d_out;

    const int* src = ei;
    const int* dst = ei + Ee;

    void *pP, *pPh, *pAL, *pAH;
    cudaGetSymbolAddress(&pP,  g_P);
    cudaGetSymbolAddress(&pPh, g_Ph);
    cudaGetSymbolAddress(&pAL, g_accL);
    cudaGetSymbolAddress(&pAH, g_accH);
    float*  Pf   = (float*)pP;                 // g_P base (3 slots)
    __half* Ph   = (__half*)pPh;               // g_Ph base (8 slots)
    float*  accL = (float*)pAL;
    float*  accH = (float*)pAH;
    const size_t SLOT = (size_t)Nn * HIDF;

    const int nblkN = (Nn + 255) / 256;   // 196
    const int nblkE = (Ee + 255) / 256;   // 3125
    const int gemmB = (Nn + 63) / 64;     // 782
    const int propB = (Nn + 7) / 8;       // 6250

    k_init<<<nblkN, 256>>>();
    k_deg<<<nblkE, 256>>>(dst);
    k_dinv<<<nblkN, 256>>>();
    k_blocksum<<<nblkN, 256>>>();
    k_scanb<<<1, 256>>>(nblkN);
    k_scanwrite<<<nblkN, 256>>>();
    k_scatter<<<nblkE, 256>>>(src, dst);
    k_coeff<<<1, 32>>>(gL, gH);

    // p_0 = h = x @ W_in + b_in   (tensor-core bf16 3-term split via mma.sync)
    k_gemm1_mma<<<gemmB, 256>>>(x, W_in, b_in, Pf, Nn);

    // Krylov chain p_j = A p_{j-1}; p0..p2 fp32, p3..p10 fp16
    k_prop_ff<<<propB, 256>>>(Pf, Pf + SLOT);                    // p1
    k_prop_ff<<<propB, 256>>>(Pf + SLOT, Pf + 2 * SLOT);         // p2
    k_prop_fh<<<propB, 256>>>(Pf + 2 * SLOT, Ph);                // p3
    for (int j = 4; j <= KK; j++)                                // p4..p10
        k_prop_hh<<<propB, 256>>>(Ph + (size_t)(j - 4) * SLOT,
                                  Ph + (size_t)(j - 3) * SLOT);

    // acc_L / acc_H + BN statistics
    k_combine<<<592, 256>>>();
    k_bnfinal<<<1, 128>>>(bns, bnb);

    // Z = relu(BN(acc) @ W_up + b_up), both branches, tensor-core path
    dim3 epg(gemmB, 2);
    k_gemm_ep_mma<<<epg, 256>>>(accL, accH, W_up, b_up, out, Nn);
}